// round 12
// baseline (speedup 1.0000x reference)
#include <cuda_runtime.h>
#include <cuda_bf16.h>
#include <math.h>
#include <stdint.h>

#define B_ 256
#define T_ 512
#define D_ 256
#define A_ 50
#define NP 56          // padded N (multiple of 8)
#define ROWS 64        // M tile per CTA (eighth of one batch)
#define KC 32          // K chunk per pipeline stage
#define PA 40          // smem pitch in bf16 (80B rows: 16B-aligned, LDSM conflict-free)
#define NCHUNK (D_ / KC)
#define CPB 8          // CTAs per batch (T_/ROWS)

typedef unsigned long long u64;

__device__ __align__(16) float g_pool_part[(B_ * T_ / ROWS) * D_];
__device__ float g_esum_part[B_ * T_ / ROWS];
__device__ int   g_cnt[B_];
__device__ __align__(16) __nv_bfloat16 g_wtb_hi[NP * D_];   // W^T [n][k] bf16 hi
__device__ __align__(16) __nv_bfloat16 g_wtb_lo[NP * D_];   // residual lo

__device__ __forceinline__ uint32_t smem_u32(const void* p) {
    uint32_t a;
    asm("{ .reg .u64 t; cvta.to.shared.u64 t, %1; cvt.u32.u64 %0, t; }" : "=r"(a) : "l"(p));
    return a;
}
__device__ __forceinline__ void ldx4(uint32_t* r, uint32_t addr) {
    asm volatile("ldmatrix.sync.aligned.m8n8.x4.shared.b16 {%0,%1,%2,%3}, [%4];"
                 : "=r"(r[0]), "=r"(r[1]), "=r"(r[2]), "=r"(r[3]) : "r"(addr));
}
__device__ __forceinline__ void ldx2(uint32_t* r, uint32_t addr) {
    asm volatile("ldmatrix.sync.aligned.m8n8.x2.shared.b16 {%0,%1}, [%2];"
                 : "=r"(r[0]), "=r"(r[1]) : "r"(addr));
}
__device__ __forceinline__ void mma16816(float* d, const uint32_t* a, const uint32_t* b) {
    asm volatile(
        "mma.sync.aligned.m16n8k16.row.col.f32.bf16.bf16.f32 "
        "{%0,%1,%2,%3}, {%4,%5,%6,%7}, {%8,%9}, {%0,%1,%2,%3};"
        : "+f"(d[0]), "+f"(d[1]), "+f"(d[2]), "+f"(d[3])
        : "r"(a[0]), "r"(a[1]), "r"(a[2]), "r"(a[3]), "r"(b[0]), "r"(b[1]));
}
__device__ __forceinline__ uint32_t pack_bf2(float vx, float vy) {
    uint32_t p;
    asm("cvt.rn.bf16x2.f32 %0, %1, %2;" : "=r"(p) : "f"(vy), "f"(vx));
    return p;
}
__device__ __forceinline__ float tanh_fast(float v) {
    float r;
    asm("tanh.approx.f32 %0, %1;" : "=f"(r) : "f"(v));
    return r;
}
#define CPASYNC16(sm_, gm_) \
    asm volatile("cp.async.cg.shared.global [%0], [%1], 16;" :: "r"(sm_), "l"(gm_))
#define CPCOMMIT() asm volatile("cp.async.commit_group;" ::: "memory")
#define CPWAIT0()  asm volatile("cp.async.wait_group 0;"  ::: "memory")

struct __align__(16) Smem {
    __nv_bfloat16 a[2][ROWS * PA];    // 2 x 5120 B
    __nv_bfloat16 bh[2][NP * PA];     // 2 x 4480 B
    __nv_bfloat16 bl[2][NP * PA];     // 2 x 4480 B
    float sb[NP], su[NP];
    float se[ROWS];
    float wsum[4];
    float pp[64][4];
    int   is_last;
};

// Prep: W^T padded bf16 hi/lo + zero batch counters.
__global__ __launch_bounds__(512) void prep_kernel(const float* __restrict__ W)
{
    int i = blockIdx.x * 512 + threadIdx.x;   // grid covers NP*D_ = 14336
    if (i < B_) g_cnt[i] = 0;
    if (i < NP * D_) {
        int n = i / D_, k = i - n * D_;
        float w = (n < A_) ? W[k * A_ + n] : 0.0f;
        __nv_bfloat16 h = __float2bfloat16(w);
        __nv_bfloat16 l = __float2bfloat16(w - __bfloat162float(h));
        g_wtb_hi[i] = h;
        g_wtb_lo[i] = l;
    }
}

__global__ __launch_bounds__(128, 5) void score_pool_mma(
    const float* __restrict__ x, const float* __restrict__ bias,
    const float* __restrict__ u, float* __restrict__ out)
{
    __shared__ Smem sm;

    const int tid  = threadIdx.x;
    const int wid  = tid >> 5;
    const int lane = tid & 31;
    const int row0 = blockIdx.x * ROWS;
    const int b    = blockIdx.x >> 3;          // CPB = 8 CTAs per batch

    if (tid < NP) {
        sm.sb[tid] = (tid < A_) ? bias[tid] : 0.0f;
        sm.su[tid] = (tid < A_) ? u[tid]    : 0.0f;
    }

    // Each warp owns one m16 row tile: rows wid*16 .. wid*16+15.
    float acc[7][4];
    #pragma unroll
    for (int nt = 0; nt < 7; ++nt)
        #pragma unroll
        for (int q = 0; q < 4; ++q) acc[nt][q] = 0.0f;

    // ldmatrix per-lane address components:
    const int sub      = lane >> 3;
    const int arow_off = (sub & 1) * 8 + (lane & 7);
    const int ak_off   = (sub >> 1) * 8;
    const int bn_off   = lane & 7;
    const int bk_off   = ((lane >> 3) & 1) * 8;

    // A staging geometry: 4 float4/thread per chunk (64 rows x 32 cols).
    const int ar  = tid >> 3;                // 0..15
    const int ac4 = (tid & 7) << 2;          // 0..28

    auto stage_b = [&](int buf, int kc) {
        const char* ghb = (const char*)g_wtb_hi;
        const char* glb = (const char*)g_wtb_lo;
        #pragma unroll
        for (int j = 0; j < 2; ++j) {
            int s = j * 128 + tid;           // 0..255, valid < 224
            if (s < 224) {
                int n = s >> 2;
                int q = (s & 3) * 16;
                u64 goff = (u64)(n * D_ + kc * KC) * 2 + q;
                uint32_t soff = (uint32_t)(n * (PA * 2) + q);
                CPASYNC16(smem_u32(sm.bh[buf]) + soff, ghb + goff);
                CPASYNC16(smem_u32(sm.bl[buf]) + soff, glb + goff);
            }
        }
        CPCOMMIT();
    };

    float4 apref[4];
    auto ldg_a = [&](int kc) {
        #pragma unroll
        for (int it = 0; it < 4; ++it)
            apref[it] = *(const float4*)(x + (size_t)(row0 + it * 16 + ar) * D_
                                         + kc * KC + ac4);
    };
    auto sts_a = [&](int buf) {
        #pragma unroll
        for (int it = 0; it < 4; ++it) {
            uint2 p;
            p.x = pack_bf2(apref[it].x, apref[it].y);
            p.y = pack_bf2(apref[it].z, apref[it].w);
            *(uint2*)&sm.a[buf][(it * 16 + ar) * PA + ac4] = p;
        }
    };

    // ---- prologue: stage chunk 0 ----
    stage_b(0, 0);
    ldg_a(0);
    sts_a(0);
    CPWAIT0();
    __syncthreads();

    for (int kc = 0; kc < NCHUNK; ++kc) {
        const int cur = kc & 1, nxt = cur ^ 1;

        if (kc + 1 < NCHUNK) {
            stage_b(nxt, kc + 1);
            ldg_a(kc + 1);
        }

        const uint32_t aB  = smem_u32(sm.a[cur]);
        const uint32_t bhB = smem_u32(sm.bh[cur]);
        const uint32_t blB = smem_u32(sm.bl[cur]);
        #pragma unroll
        for (int ks = 0; ks < 2; ++ks) {
            const int k0 = ks * 16;
            uint32_t bhf[7][2], blf[7][2];
            #pragma unroll
            for (int nt = 0; nt < 7; ++nt) {
                uint32_t off = (uint32_t)(((nt * 8 + bn_off) * PA + k0 + bk_off) * 2);
                ldx2(bhf[nt], bhB + off);
                ldx2(blf[nt], blB + off);
            }
            uint32_t aoff = (uint32_t)(((wid * 16 + arow_off) * PA + k0 + ak_off) * 2);
            uint32_t av[4];
            ldx4(av, aB + aoff);
            #pragma unroll
            for (int nt = 0; nt < 7; ++nt) {
                mma16816(acc[nt], av, bhf[nt]);
                mma16816(acc[nt], av, blf[nt]);
            }
        }

        if (kc + 1 < NCHUNK) {
            sts_a(nxt);
            CPWAIT0();
            __syncthreads();
        }
    }

    // ---- epilogue: scores. D frag: row=lane/4 (+8), col=2*(lane&3)+8*nt (+1).
    {
        float plo = 0.0f, phi = 0.0f;
        #pragma unroll
        for (int nt = 0; nt < 7; ++nt) {
            int c = nt * 8 + 2 * (lane & 3);
            plo += tanh_fast(acc[nt][0] + sm.sb[c])     * sm.su[c];
            plo += tanh_fast(acc[nt][1] + sm.sb[c + 1]) * sm.su[c + 1];
            phi += tanh_fast(acc[nt][2] + sm.sb[c])     * sm.su[c];
            phi += tanh_fast(acc[nt][3] + sm.sb[c + 1]) * sm.su[c + 1];
        }
        plo += __shfl_xor_sync(0xFFFFFFFFu, plo, 1);
        plo += __shfl_xor_sync(0xFFFFFFFFu, plo, 2);
        phi += __shfl_xor_sync(0xFFFFFFFFu, phi, 1);
        phi += __shfl_xor_sync(0xFFFFFFFFu, phi, 2);
        if ((lane & 3) == 0) {
            int r = wid * 16 + (lane >> 2);
            sm.se[r]     = __expf(plo);
            sm.se[r + 8] = __expf(phi);
        }
    }
    __syncthreads();

    // Block sum of e over 64 rows -> per-CTA partial.
    float s = (tid < ROWS) ? sm.se[tid] : 0.0f;
    #pragma unroll
    for (int o = 16; o; o >>= 1) s += __shfl_xor_sync(0xFFFFFFFFu, s, o);
    if (lane == 0) sm.wsum[wid] = s;
    __syncthreads();
    if (tid == 0)
        g_esum_part[blockIdx.x] = sm.wsum[0] + sm.wsum[1] + sm.wsum[2] + sm.wsum[3];

    // ---- fused pool over this CTA's 64 rows (x L2-hot).
    const int tc = tid >> 6;                 // 0..1 : rows half
    const int g  = tid & 63;                 // cols group
    const float* xb = x + (size_t)(row0 + tc * 32) * D_ + g * 4;

    float ax = 0.0f, ay = 0.0f, az = 0.0f, aw = 0.0f;
    #pragma unroll 8
    for (int tt = 0; tt < 32; ++tt) {
        float w  = sm.se[tc * 32 + tt];
        float4 v = *(const float4*)(xb + (size_t)tt * D_);
        ax += v.x * w; ay += v.y * w; az += v.z * w; aw += v.w * w;
    }
    if (tc == 1) {
        sm.pp[g][0] = ax; sm.pp[g][1] = ay; sm.pp[g][2] = az; sm.pp[g][3] = aw;
    }
    __syncthreads();
    if (tc == 0) {
        float4 r;
        r.x = ax + sm.pp[g][0];
        r.y = ay + sm.pp[g][1];
        r.z = az + sm.pp[g][2];
        r.w = aw + sm.pp[g][3];
        *(float4*)&g_pool_part[blockIdx.x * D_ + g * 4] = r;
    }

    // ---- last CTA of this batch finalizes out[b,:].
    __syncthreads();
    if (tid == 0) {
        __threadfence();
        int old = atomicAdd(&g_cnt[b], 1);
        sm.is_last = (old == CPB - 1);
    }
    __syncthreads();
    if (sm.is_last) {
        __threadfence();
        const float* ep = &g_esum_part[CPB * b];
        float es = 0.0f;
        #pragma unroll
        for (int i = 0; i < CPB; ++i) es += ep[i];
        float inv = 1.0f / (es + 1e-7f);
        int d = tid * 2;
        const float* pp = &g_pool_part[(CPB * b) * D_ + d];
        float p0 = 0.0f, p1 = 0.0f;
        #pragma unroll
        for (int i = 0; i < CPB; ++i) {
            p0 += pp[i * D_];
            p1 += pp[i * D_ + 1];
        }
        float2 r;
        r.x = p0 * inv;
        r.y = p1 * inv;
        *(float2*)&out[b * D_ + d] = r;
    }
}

extern "C" void kernel_launch(void* const* d_in, const int* in_sizes, int n_in,
                              void* d_out, int out_size)
{
    const float* x  = (const float*)d_in[0];
    const float* W  = (const float*)d_in[1];
    const float* bb = (const float*)d_in[2];
    const float* u  = (const float*)d_in[3];
    float* out = (float*)d_out;

    prep_kernel<<<(NP * D_ + 511) / 512, 512>>>(W);
    score_pool_mma<<<(B_ * T_) / ROWS, 128>>>(x, bb, u, out);
}

// round 14
// speedup vs baseline: 1.0345x; 1.0345x over previous
#include <cuda_runtime.h>
#include <cuda_bf16.h>
#include <math.h>
#include <stdint.h>

#define B_ 256
#define T_ 512
#define D_ 256
#define A_ 50
#define NP 56          // padded N (multiple of 8)
#define ROWS 128       // M tile per CTA
#define KC 32          // K chunk per pipeline stage
#define PA 40          // smem pitch in bf16 (80B rows: 16B-aligned, LDSM conflict-free)
#define NCHUNK (D_ / KC)

typedef unsigned long long u64;

__device__ __align__(16) float g_pool_part[(B_ * T_ / ROWS) * D_];
__device__ float g_esum_part[B_ * T_ / ROWS];
__device__ int   g_cnt[B_];
__device__ __align__(16) __nv_bfloat16 g_wtb_hi[NP * D_];   // W^T [n][k] bf16 hi
__device__ __align__(16) __nv_bfloat16 g_wtb_lo[NP * D_];   // residual lo

__device__ __forceinline__ uint32_t smem_u32(const void* p) {
    uint32_t a;
    asm("{ .reg .u64 t; cvta.to.shared.u64 t, %1; cvt.u32.u64 %0, t; }" : "=r"(a) : "l"(p));
    return a;
}
__device__ __forceinline__ void ldx4(uint32_t* r, uint32_t addr) {
    asm volatile("ldmatrix.sync.aligned.m8n8.x4.shared.b16 {%0,%1,%2,%3}, [%4];"
                 : "=r"(r[0]), "=r"(r[1]), "=r"(r[2]), "=r"(r[3]) : "r"(addr));
}
__device__ __forceinline__ void mma16816(float* d, const uint32_t* a, const uint32_t* b) {
    asm volatile(
        "mma.sync.aligned.m16n8k16.row.col.f32.bf16.bf16.f32 "
        "{%0,%1,%2,%3}, {%4,%5,%6,%7}, {%8,%9}, {%0,%1,%2,%3};"
        : "+f"(d[0]), "+f"(d[1]), "+f"(d[2]), "+f"(d[3])
        : "r"(a[0]), "r"(a[1]), "r"(a[2]), "r"(a[3]), "r"(b[0]), "r"(b[1]));
}
__device__ __forceinline__ uint32_t pack_bf2(float vx, float vy) {
    uint32_t p;
    asm("cvt.rn.bf16x2.f32 %0, %1, %2;" : "=r"(p) : "f"(vy), "f"(vx));
    return p;
}
__device__ __forceinline__ float tanh_fast(float v) {
    float r;
    asm("tanh.approx.f32 %0, %1;" : "=f"(r) : "f"(v));
    return r;
}
#define CPASYNC16(sm_, gm_) \
    asm volatile("cp.async.cg.shared.global [%0], [%1], 16;" :: "r"(sm_), "l"(gm_))
#define CPCOMMIT() asm volatile("cp.async.commit_group;" ::: "memory")
#define CPWAIT0()  asm volatile("cp.async.wait_group 0;"  ::: "memory")

struct __align__(16) Smem {
    __nv_bfloat16 a[2][ROWS * PA];    // 2 x 10240 B
    __nv_bfloat16 bh[2][NP * PA];     // 2 x 4480 B
    __nv_bfloat16 bl[2][NP * PA];     // 2 x 4480 B
    float sb[NP], su[NP];
    float se[ROWS];
    float wsum[4];
    float pp[64][4];
    int   is_last;
};

// Prep: W^T padded bf16 hi/lo + zero batch counters.
__global__ __launch_bounds__(512) void prep_kernel(const float* __restrict__ W)
{
    int i = blockIdx.x * 512 + threadIdx.x;   // grid covers NP*D_ = 14336
    if (i < B_) g_cnt[i] = 0;
    if (i < NP * D_) {
        int n = i / D_, k = i - n * D_;
        float w = (n < A_) ? W[k * A_ + n] : 0.0f;
        __nv_bfloat16 h = __float2bfloat16(w);
        __nv_bfloat16 l = __float2bfloat16(w - __bfloat162float(h));
        g_wtb_hi[i] = h;
        g_wtb_lo[i] = l;
    }
}

__global__ __launch_bounds__(128, 4) void score_pool_mma(
    const float* __restrict__ x, const float* __restrict__ bias,
    const float* __restrict__ u, float* __restrict__ out)
{
    __shared__ Smem sm;

    const int tid  = threadIdx.x;
    const int wid  = tid >> 5;
    const int lane = tid & 31;
    const int row0 = blockIdx.x * ROWS;
    const int b    = blockIdx.x >> 2;

    if (tid < NP) {
        sm.sb[tid] = (tid < A_) ? bias[tid] : 0.0f;
        sm.su[tid] = (tid < A_) ? u[tid]    : 0.0f;
    }

    float acc[2][7][4];
    #pragma unroll
    for (int mt = 0; mt < 2; ++mt)
        #pragma unroll
        for (int nt = 0; nt < 7; ++nt)
            #pragma unroll
            for (int q = 0; q < 4; ++q) acc[mt][nt][q] = 0.0f;

    // ldmatrix lane address components.
    const int sub      = lane >> 3;                  // which 8x8 matrix this lane addresses
    const int arow_off = (sub & 1) * 8 + (lane & 7); // A x4: row
    const int ak_off   = (sub >> 1) * 8;             // A x4: k-half
    const int b_row    = lane & 7;                   // B combined x4: row within n-tile
    const int b_khalf  = (sub & 1) * 8;              // matrices 0/2 -> k0, 1/3 -> k0+8
    const int b_is_lo  = sub >> 1;                   // matrices 2,3 -> bl

    // A staging geometry: 8 float4/thread per chunk.
    const int ar  = tid >> 3;
    const int ac4 = (tid & 7) << 2;

    auto stage_b = [&](int buf, int kc) {
        const char* ghb = (const char*)g_wtb_hi;
        const char* glb = (const char*)g_wtb_lo;
        #pragma unroll
        for (int j = 0; j < 2; ++j) {
            int s = j * 128 + tid;          // 0..255, valid < 224
            if (s < 224) {
                int n = s >> 2;
                int q = (s & 3) * 16;
                u64 goff = (u64)(n * D_ + kc * KC) * 2 + q;
                uint32_t soff = (uint32_t)(n * (PA * 2) + q);
                CPASYNC16(smem_u32(sm.bh[buf]) + soff, ghb + goff);
                CPASYNC16(smem_u32(sm.bl[buf]) + soff, glb + goff);
            }
        }
        CPCOMMIT();
    };

    float4 apref[8];
    auto ldg_a = [&](int kc) {
        #pragma unroll
        for (int it = 0; it < 8; ++it)
            apref[it] = *(const float4*)(x + (size_t)(row0 + it * 16 + ar) * D_
                                         + kc * KC + ac4);
    };
    auto sts_a = [&](int buf) {
        #pragma unroll
        for (int it = 0; it < 8; ++it) {
            uint2 p;
            p.x = pack_bf2(apref[it].x, apref[it].y);
            p.y = pack_bf2(apref[it].z, apref[it].w);
            *(uint2*)&sm.a[buf][(it * 16 + ar) * PA + ac4] = p;
        }
    };

    // ---- prologue: stage chunk 0 ----
    stage_b(0, 0);
    ldg_a(0);
    sts_a(0);
    CPWAIT0();
    __syncthreads();

    for (int kc = 0; kc < NCHUNK; ++kc) {
        const int cur = kc & 1, nxt = cur ^ 1;

        if (kc + 1 < NCHUNK) {
            stage_b(nxt, kc + 1);
            ldg_a(kc + 1);
        }

        const uint32_t aB  = smem_u32(sm.a[cur]);
        const uint32_t bhB = smem_u32(sm.bh[cur]);
        const uint32_t blB = smem_u32(sm.bl[cur]);
        #pragma unroll
        for (int ks = 0; ks < 2; ++ks) {
            const int k0 = ks * 16;
            // Combined hi/lo B fragments: one x4 per n-tile (r0,r1=bh; r2,r3=bl).
            uint32_t bf[7][4];
            #pragma unroll
            for (int nt = 0; nt < 7; ++nt) {
                uint32_t base = b_is_lo ? blB : bhB;
                uint32_t off  = (uint32_t)(((nt * 8 + b_row) * PA + k0 + b_khalf) * 2);
                ldx4(bf[nt], base + off);
            }
            #pragma unroll
            for (int mt = 0; mt < 2; ++mt) {
                uint32_t off = (uint32_t)(((wid * 32 + mt * 16 + arow_off) * PA
                                           + k0 + ak_off) * 2);
                uint32_t av[4];
                ldx4(av, aB + off);
                #pragma unroll
                for (int nt = 0; nt < 7; ++nt) {
                    mma16816(acc[mt][nt], av, &bf[nt][0]);   // x @ W_hi
                    mma16816(acc[mt][nt], av, &bf[nt][2]);   // x @ W_lo
                }
            }
        }

        if (kc + 1 < NCHUNK) {
            sts_a(nxt);
            CPWAIT0();
            __syncthreads();
        }
    }

    // ---- epilogue: scores.
    #pragma unroll
    for (int mt = 0; mt < 2; ++mt) {
        float plo = 0.0f, phi = 0.0f;
        #pragma unroll
        for (int nt = 0; nt < 7; ++nt) {
            int c = nt * 8 + 2 * (lane & 3);
            plo += tanh_fast(acc[mt][nt][0] + sm.sb[c])     * sm.su[c];
            plo += tanh_fast(acc[mt][nt][1] + sm.sb[c + 1]) * sm.su[c + 1];
            phi += tanh_fast(acc[mt][nt][2] + sm.sb[c])     * sm.su[c];
            phi += tanh_fast(acc[mt][nt][3] + sm.sb[c + 1]) * sm.su[c + 1];
        }
        plo += __shfl_xor_sync(0xFFFFFFFFu, plo, 1);
        plo += __shfl_xor_sync(0xFFFFFFFFu, plo, 2);
        phi += __shfl_xor_sync(0xFFFFFFFFu, phi, 1);
        phi += __shfl_xor_sync(0xFFFFFFFFu, phi, 2);
        if ((lane & 3) == 0) {
            int r = wid * 32 + mt * 16 + (lane >> 2);
            sm.se[r]     = __expf(plo);
            sm.se[r + 8] = __expf(phi);
        }
    }
    __syncthreads();

    float e = sm.se[tid];
    float s = e;
    #pragma unroll
    for (int o = 16; o; o >>= 1) s += __shfl_xor_sync(0xFFFFFFFFu, s, o);
    if (lane == 0) sm.wsum[wid] = s;
    __syncthreads();
    if (tid == 0)
        g_esum_part[blockIdx.x] = sm.wsum[0] + sm.wsum[1] + sm.wsum[2] + sm.wsum[3];

    // ---- fused pool over this CTA's 128 rows (x L2-hot, fp32 — precision-safe).
    const int tc = tid >> 6;
    const int g  = tid & 63;
    const float* xb = x + (size_t)(row0 + tc * 64) * D_ + g * 4;

    float ax = 0.0f, ay = 0.0f, az = 0.0f, aw = 0.0f;
    #pragma unroll 8
    for (int tt = 0; tt < 64; ++tt) {
        float w  = sm.se[tc * 64 + tt];
        float4 v = *(const float4*)(xb + (size_t)tt * D_);
        ax += v.x * w; ay += v.y * w; az += v.z * w; aw += v.w * w;
    }
    if (tc == 1) {
        sm.pp[g][0] = ax; sm.pp[g][1] = ay; sm.pp[g][2] = az; sm.pp[g][3] = aw;
    }
    __syncthreads();
    if (tc == 0) {
        float4 r;
        r.x = ax + sm.pp[g][0];
        r.y = ay + sm.pp[g][1];
        r.z = az + sm.pp[g][2];
        r.w = aw + sm.pp[g][3];
        *(float4*)&g_pool_part[blockIdx.x * D_ + g * 4] = r;
    }

    // ---- last CTA of this batch finalizes out[b,:].
    __syncthreads();
    if (tid == 0) {
        __threadfence();
        int old = atomicAdd(&g_cnt[b], 1);
        sm.is_last = (old == 3);
    }
    __syncthreads();
    if (sm.is_last) {
        __threadfence();
        const float* ep = &g_esum_part[4 * b];
        float inv = 1.0f / (ep[0] + ep[1] + ep[2] + ep[3] + 1e-7f);
        int d = tid * 2;
        const float* pp = &g_pool_part[(4 * b) * D_ + d];
        float p0 = pp[0]     + pp[D_]     + pp[2 * D_]     + pp[3 * D_];
        float p1 = pp[1]     + pp[D_ + 1] + pp[2 * D_ + 1] + pp[3 * D_ + 1];
        float2 r;
        r.x = p0 * inv;
        r.y = p1 * inv;
        *(float2*)&out[b * D_ + d] = r;
    }
}

extern "C" void kernel_launch(void* const* d_in, const int* in_sizes, int n_in,
                              void* d_out, int out_size)
{
    const float* x  = (const float*)d_in[0];
    const float* W  = (const float*)d_in[1];
    const float* bb = (const float*)d_in[2];
    const float* u  = (const float*)d_in[3];
    float* out = (float*)d_out;

    prep_kernel<<<(NP * D_ + 511) / 512, 512>>>(W);
    score_pool_mma<<<(B_ * T_) / ROWS, 128>>>(x, bb, u, out);
}

// round 15
// speedup vs baseline: 1.3548x; 1.3097x over previous
#include <cuda_runtime.h>
#include <cuda_bf16.h>
#include <math.h>
#include <stdint.h>

#define B_ 256
#define T_ 512
#define D_ 256
#define A_ 50
#define NP 56          // padded N (multiple of 8)
#define ROWS 128       // M tile per CTA
#define KC 32          // K chunk per pipeline stage
#define PA 40          // smem pitch in bf16 (80B rows: 16B-aligned, LDSM conflict-free)
#define NCHUNK (D_ / KC)

typedef unsigned long long u64;

__device__ __align__(16) float g_pool_part[(B_ * T_ / ROWS) * D_];
__device__ float g_esum_part[B_ * T_ / ROWS];
__device__ int   g_cnt[B_];
__device__ __align__(16) __nv_bfloat16 g_wtb[NP * D_];   // W^T [n][k] bf16

__device__ __forceinline__ uint32_t smem_u32(const void* p) {
    uint32_t a;
    asm("{ .reg .u64 t; cvta.to.shared.u64 t, %1; cvt.u32.u64 %0, t; }" : "=r"(a) : "l"(p));
    return a;
}
__device__ __forceinline__ void ldx4(uint32_t* r, uint32_t addr) {
    asm volatile("ldmatrix.sync.aligned.m8n8.x4.shared.b16 {%0,%1,%2,%3}, [%4];"
                 : "=r"(r[0]), "=r"(r[1]), "=r"(r[2]), "=r"(r[3]) : "r"(addr));
}
__device__ __forceinline__ void ldx2(uint32_t* r, uint32_t addr) {
    asm volatile("ldmatrix.sync.aligned.m8n8.x2.shared.b16 {%0,%1}, [%2];"
                 : "=r"(r[0]), "=r"(r[1]) : "r"(addr));
}
__device__ __forceinline__ void mma16816(float* d, const uint32_t* a, const uint32_t* b) {
    asm volatile(
        "mma.sync.aligned.m16n8k16.row.col.f32.bf16.bf16.f32 "
        "{%0,%1,%2,%3}, {%4,%5,%6,%7}, {%8,%9}, {%0,%1,%2,%3};"
        : "+f"(d[0]), "+f"(d[1]), "+f"(d[2]), "+f"(d[3])
        : "r"(a[0]), "r"(a[1]), "r"(a[2]), "r"(a[3]), "r"(b[0]), "r"(b[1]));
}
__device__ __forceinline__ uint32_t pack_bf2(float vx, float vy) {
    uint32_t p;
    asm("cvt.rn.bf16x2.f32 %0, %1, %2;" : "=r"(p) : "f"(vy), "f"(vx));
    return p;
}
__device__ __forceinline__ float tanh_fast(float v) {
    float r;
    asm("tanh.approx.f32 %0, %1;" : "=f"(r) : "f"(v));
    return r;
}
#define CPASYNC16(sm_, gm_) \
    asm volatile("cp.async.cg.shared.global [%0], [%1], 16;" :: "r"(sm_), "l"(gm_))
#define CPCOMMIT() asm volatile("cp.async.commit_group;" ::: "memory")
#define CPWAIT0()  asm volatile("cp.async.wait_group 0;"  ::: "memory")

struct __align__(16) Smem {
    __nv_bfloat16 a[2][ROWS * PA];    // 2 x 10240 B
    __nv_bfloat16 bh[2][NP * PA];     // 2 x 4480 B
    float sb[NP], su[NP];
    float se[ROWS];
    float wsum[4];
    float pp[64][4];
    int   is_last;
};

// Prep: W^T padded bf16 + zero batch counters.
__global__ __launch_bounds__(512) void prep_kernel(const float* __restrict__ W)
{
    int i = blockIdx.x * 512 + threadIdx.x;   // grid covers NP*D_ = 14336
    if (i < B_) g_cnt[i] = 0;
    if (i < NP * D_) {
        int n = i / D_, k = i - n * D_;
        float w = (n < A_) ? W[k * A_ + n] : 0.0f;
        g_wtb[i] = __float2bfloat16(w);
    }
}

__global__ __launch_bounds__(128, 4) void score_pool_mma(
    const float* __restrict__ x, const float* __restrict__ bias,
    const float* __restrict__ u, float* __restrict__ out)
{
    __shared__ Smem sm;

    const int tid  = threadIdx.x;
    const int wid  = tid >> 5;
    const int lane = tid & 31;
    const int row0 = blockIdx.x * ROWS;
    const int b    = blockIdx.x >> 2;

    if (tid < NP) {
        sm.sb[tid] = (tid < A_) ? bias[tid] : 0.0f;
        sm.su[tid] = (tid < A_) ? u[tid]    : 0.0f;
    }

    float acc[2][7][4];
    #pragma unroll
    for (int mt = 0; mt < 2; ++mt)
        #pragma unroll
        for (int nt = 0; nt < 7; ++nt)
            #pragma unroll
            for (int q = 0; q < 4; ++q) acc[mt][nt][q] = 0.0f;

    // ldmatrix per-lane address components (same structure as the 45.8us R11 kernel):
    const int sub      = lane >> 3;
    const int arow_off = (sub & 1) * 8 + (lane & 7);
    const int ak_off   = (sub >> 1) * 8;
    const int bn_off   = lane & 7;
    const int bk_off   = ((lane >> 3) & 1) * 8;

    // A staging geometry: 8 float4/thread per chunk.
    const int ar  = tid >> 3;
    const int ac4 = (tid & 7) << 2;

    auto stage_b = [&](int buf, int kc) {
        const char* ghb = (const char*)g_wtb;
        #pragma unroll
        for (int j = 0; j < 2; ++j) {
            int s = j * 128 + tid;          // 0..255, valid < 224
            if (s < 224) {
                int n = s >> 2;
                int q = (s & 3) * 16;
                u64 goff = (u64)(n * D_ + kc * KC) * 2 + q;
                uint32_t soff = (uint32_t)(n * (PA * 2) + q);
                CPASYNC16(smem_u32(sm.bh[buf]) + soff, ghb + goff);
            }
        }
        CPCOMMIT();
    };

    float4 apref[8];
    auto ldg_a = [&](int kc) {
        #pragma unroll
        for (int it = 0; it < 8; ++it)
            apref[it] = *(const float4*)(x + (size_t)(row0 + it * 16 + ar) * D_
                                         + kc * KC + ac4);
    };
    auto sts_a = [&](int buf) {
        #pragma unroll
        for (int it = 0; it < 8; ++it) {
            uint2 p;
            p.x = pack_bf2(apref[it].x, apref[it].y);
            p.y = pack_bf2(apref[it].z, apref[it].w);
            *(uint2*)&sm.a[buf][(it * 16 + ar) * PA + ac4] = p;
        }
    };

    // ---- prologue: stage chunk 0 ----
    stage_b(0, 0);
    ldg_a(0);
    sts_a(0);
    CPWAIT0();
    __syncthreads();

    for (int kc = 0; kc < NCHUNK; ++kc) {
        const int cur = kc & 1, nxt = cur ^ 1;

        if (kc + 1 < NCHUNK) {
            stage_b(nxt, kc + 1);
            ldg_a(kc + 1);
        }

        const uint32_t aB  = smem_u32(sm.a[cur]);
        const uint32_t bhB = smem_u32(sm.bh[cur]);
        #pragma unroll
        for (int ks = 0; ks < 2; ++ks) {
            const int k0 = ks * 16;
            uint32_t bhf[7][2];
            #pragma unroll
            for (int nt = 0; nt < 7; ++nt) {
                uint32_t off = (uint32_t)(((nt * 8 + bn_off) * PA + k0 + bk_off) * 2);
                ldx2(bhf[nt], bhB + off);
            }
            #pragma unroll
            for (int mt = 0; mt < 2; ++mt) {
                uint32_t off = (uint32_t)(((wid * 32 + mt * 16 + arow_off) * PA
                                           + k0 + ak_off) * 2);
                uint32_t av[4];
                ldx4(av, aB + off);
                #pragma unroll
                for (int nt = 0; nt < 7; ++nt)
                    mma16816(acc[mt][nt], av, bhf[nt]);   // x_bf16 @ W_bf16
            }
        }

        if (kc + 1 < NCHUNK) {
            sts_a(nxt);
            CPWAIT0();
            __syncthreads();
        }
    }

    // ---- epilogue: scores.
    #pragma unroll
    for (int mt = 0; mt < 2; ++mt) {
        float plo = 0.0f, phi = 0.0f;
        #pragma unroll
        for (int nt = 0; nt < 7; ++nt) {
            int c = nt * 8 + 2 * (lane & 3);
            plo += tanh_fast(acc[mt][nt][0] + sm.sb[c])     * sm.su[c];
            plo += tanh_fast(acc[mt][nt][1] + sm.sb[c + 1]) * sm.su[c + 1];
            phi += tanh_fast(acc[mt][nt][2] + sm.sb[c])     * sm.su[c];
            phi += tanh_fast(acc[mt][nt][3] + sm.sb[c + 1]) * sm.su[c + 1];
        }
        plo += __shfl_xor_sync(0xFFFFFFFFu, plo, 1);
        plo += __shfl_xor_sync(0xFFFFFFFFu, plo, 2);
        phi += __shfl_xor_sync(0xFFFFFFFFu, phi, 1);
        phi += __shfl_xor_sync(0xFFFFFFFFu, phi, 2);
        if ((lane & 3) == 0) {
            int r = wid * 32 + mt * 16 + (lane >> 2);
            sm.se[r]     = __expf(plo);
            sm.se[r + 8] = __expf(phi);
        }
    }
    __syncthreads();

    float e = sm.se[tid];
    float s = e;
    #pragma unroll
    for (int o = 16; o; o >>= 1) s += __shfl_xor_sync(0xFFFFFFFFu, s, o);
    if (lane == 0) sm.wsum[wid] = s;
    __syncthreads();
    if (tid == 0)
        g_esum_part[blockIdx.x] = sm.wsum[0] + sm.wsum[1] + sm.wsum[2] + sm.wsum[3];

    // ---- fused pool over this CTA's 128 rows (x L2-hot, fp32).
    const int tc = tid >> 6;
    const int g  = tid & 63;
    const float* xb = x + (size_t)(row0 + tc * 64) * D_ + g * 4;

    float ax = 0.0f, ay = 0.0f, az = 0.0f, aw = 0.0f;
    #pragma unroll 8
    for (int tt = 0; tt < 64; ++tt) {
        float w  = sm.se[tc * 64 + tt];
        float4 v = *(const float4*)(xb + (size_t)tt * D_);
        ax += v.x * w; ay += v.y * w; az += v.z * w; aw += v.w * w;
    }
    if (tc == 1) {
        sm.pp[g][0] = ax; sm.pp[g][1] = ay; sm.pp[g][2] = az; sm.pp[g][3] = aw;
    }
    __syncthreads();
    if (tc == 0) {
        float4 r;
        r.x = ax + sm.pp[g][0];
        r.y = ay + sm.pp[g][1];
        r.z = az + sm.pp[g][2];
        r.w = aw + sm.pp[g][3];
        *(float4*)&g_pool_part[blockIdx.x * D_ + g * 4] = r;
    }

    // ---- last CTA of this batch finalizes out[b,:].
    __syncthreads();
    if (tid == 0) {
        __threadfence();
        int old = atomicAdd(&g_cnt[b], 1);
        sm.is_last = (old == 3);
    }
    __syncthreads();
    if (sm.is_last) {
        __threadfence();
        const float* ep = &g_esum_part[4 * b];
        float inv = 1.0f / (ep[0] + ep[1] + ep[2] + ep[3] + 1e-7f);
        int d = tid * 2;
        const float* pp = &g_pool_part[(4 * b) * D_ + d];
        float p0 = pp[0]     + pp[D_]     + pp[2 * D_]     + pp[3 * D_];
        float p1 = pp[1]     + pp[D_ + 1] + pp[2 * D_ + 1] + pp[3 * D_ + 1];
        float2 r;
        r.x = p0 * inv;
        r.y = p1 * inv;
        *(float2*)&out[b * D_ + d] = r;
    }
}

extern "C" void kernel_launch(void* const* d_in, const int* in_sizes, int n_in,
                              void* d_out, int out_size)
{
    const float* x  = (const float*)d_in[0];
    const float* W  = (const float*)d_in[1];
    const float* bb = (const float*)d_in[2];
    const float* u  = (const float*)d_in[3];
    float* out = (float*)d_out;

    prep_kernel<<<(NP * D_ + 511) / 512, 512>>>(W);
    score_pool_mma<<<(B_ * T_) / ROWS, 128>>>(x, bb, u, out);
}

// round 16
// speedup vs baseline: 1.3559x; 1.0008x over previous
#include <cuda_runtime.h>
#include <cuda_bf16.h>
#include <math.h>
#include <stdint.h>

#define B_ 256
#define T_ 512
#define D_ 256
#define A_ 50
#define NP 56          // padded N (multiple of 8)
#define ROWS 128       // M tile per CTA
#define KC 32          // K chunk per pipeline stage
#define PB 40          // B smem pitch in bf16 (80B rows: 16B-aligned, LDSM conflict-free)
#define NCHUNK (D_ / KC)

typedef unsigned long long u64;

__device__ __align__(16) float g_pool_part[(B_ * T_ / ROWS) * D_];
__device__ float g_esum_part[B_ * T_ / ROWS];
__device__ int   g_cnt[B_];
__device__ __align__(16) __nv_bfloat16 g_wtb[NP * D_];   // W^T [n][k] bf16

__device__ __forceinline__ uint32_t smem_u32(const void* p) {
    uint32_t a;
    asm("{ .reg .u64 t; cvta.to.shared.u64 t, %1; cvt.u32.u64 %0, t; }" : "=r"(a) : "l"(p));
    return a;
}
__device__ __forceinline__ void ldx2(uint32_t* r, uint32_t addr) {
    asm volatile("ldmatrix.sync.aligned.m8n8.x2.shared.b16 {%0,%1}, [%2];"
                 : "=r"(r[0]), "=r"(r[1]) : "r"(addr));
}
__device__ __forceinline__ void mma16816(float* d, const uint32_t* a, const uint32_t* b) {
    asm volatile(
        "mma.sync.aligned.m16n8k16.row.col.f32.bf16.bf16.f32 "
        "{%0,%1,%2,%3}, {%4,%5,%6,%7}, {%8,%9}, {%0,%1,%2,%3};"
        : "+f"(d[0]), "+f"(d[1]), "+f"(d[2]), "+f"(d[3])
        : "r"(a[0]), "r"(a[1]), "r"(a[2]), "r"(a[3]), "r"(b[0]), "r"(b[1]));
}
__device__ __forceinline__ uint32_t pack_bf2(float vx, float vy) {
    uint32_t p;
    asm("cvt.rn.bf16x2.f32 %0, %1, %2;" : "=r"(p) : "f"(vy), "f"(vx));
    return p;
}
__device__ __forceinline__ float tanh_fast(float v) {
    float r;
    asm("tanh.approx.f32 %0, %1;" : "=f"(r) : "f"(v));
    return r;
}
#define CPASYNC16(sm_, gm_) \
    asm volatile("cp.async.cg.shared.global [%0], [%1], 16;" :: "r"(sm_), "l"(gm_))
#define CPCOMMIT() asm volatile("cp.async.commit_group;" ::: "memory")
#define CPWAIT1()  asm volatile("cp.async.wait_group 1;"  ::: "memory")
#define CPWAIT0()  asm volatile("cp.async.wait_group 0;"  ::: "memory")

struct __align__(16) Smem {
    float af[2][ROWS * KC];           // 2 x 16384 B : fp32 x chunk, XOR-swizzled cols
    __nv_bfloat16 bh[2][NP * PB];     // 2 x 4480 B
    float sb[NP], su[NP];
    float se[ROWS];
    float wsum[4];
    float pp[64][4];
    int   is_last;
};

// Prep: W^T padded bf16 + zero batch counters.
__global__ __launch_bounds__(512) void prep_kernel(const float* __restrict__ W)
{
    int i = blockIdx.x * 512 + threadIdx.x;   // grid covers NP*D_ = 14336
    if (i < B_) g_cnt[i] = 0;
    if (i < NP * D_) {
        int n = i / D_, k = i - n * D_;
        float w = (n < A_) ? W[k * A_ + n] : 0.0f;
        g_wtb[i] = __float2bfloat16(w);
    }
}

__global__ __launch_bounds__(128, 5) void score_pool_mma(
    const float* __restrict__ x, const float* __restrict__ bias,
    const float* __restrict__ u, float* __restrict__ out)
{
    __shared__ Smem sm;

    const int tid  = threadIdx.x;
    const int wid  = tid >> 5;
    const int lane = tid & 31;
    const int row0 = blockIdx.x * ROWS;
    const int b    = blockIdx.x >> 2;

    if (tid < NP) {
        sm.sb[tid] = (tid < A_) ? bias[tid] : 0.0f;
        sm.su[tid] = (tid < A_) ? u[tid]    : 0.0f;
    }

    float acc[2][7][4];
    #pragma unroll
    for (int mt = 0; mt < 2; ++mt)
        #pragma unroll
        for (int nt = 0; nt < 7; ++nt)
            #pragma unroll
            for (int q = 0; q < 4; ++q) acc[mt][nt][q] = 0.0f;

    // B ldmatrix per-lane address components (unchanged from R15):
    const int bn_off = lane & 7;
    const int bk_off = ((lane >> 3) & 1) * 8;

    // A fragment geometry: row = wid*32 + mt*16 + lane/4 (+8); col = ks*16 + 2*(lane&3) (+8).
    // Swizzle: col' = col ^ ((row&3)<<3); row&3 invariant under +8/+16 -> one constant.
    const int frow = lane >> 2;                    // 0..7
    const int sw   = (frow & 3) << 3;              // XOR swizzle for this thread
    const int fcol = 2 * (lane & 3);

    // A cp.async geometry: 1024 16B slots; 8 per thread; r = s>>3, c4 = (s&7)*4.
    const int ar  = tid >> 3;                      // rows tid/8, +16 per it
    const int ac4 = (tid & 7) << 2;

    auto stage = [&](int buf, int kc) {
        // A chunk: 128 rows x 32 fp32, swizzled store.
        const uint32_t afB = smem_u32(sm.af[buf]);
        #pragma unroll
        for (int it = 0; it < 8; ++it) {
            int r = it * 16 + ar;
            uint32_t doff = (uint32_t)((r * KC + (ac4 ^ ((r & 3) << 3))) * 4);
            const float* g = x + (size_t)(row0 + r) * D_ + kc * KC + ac4;
            CPASYNC16(afB + doff, g);
        }
        // B chunk: 224 16B slots; 2 per thread.
        const char* ghb = (const char*)g_wtb;
        const uint32_t bhB = smem_u32(sm.bh[buf]);
        #pragma unroll
        for (int j = 0; j < 2; ++j) {
            int s = j * 128 + tid;
            if (s < 224) {
                int n = s >> 2;
                int q = (s & 3) * 16;
                CPASYNC16(bhB + (uint32_t)(n * (PB * 2) + q),
                          ghb + (u64)(n * D_ + kc * KC) * 2 + q);
            }
        }
        CPCOMMIT();
    };

    // ---- prologue ----
    stage(0, 0);

    for (int kc = 0; kc < NCHUNK; ++kc) {
        const int cur = kc & 1;

        if (kc + 1 < NCHUNK) {
            stage(cur ^ 1, kc + 1);
            CPWAIT1();               // cur complete; next still in flight
        } else {
            CPWAIT0();
        }
        __syncthreads();

        const float*   A   = sm.af[cur];
        const uint32_t bhB = smem_u32(sm.bh[cur]);
        #pragma unroll
        for (int ks = 0; ks < 2; ++ks) {
            const int k0 = ks * 16;
            uint32_t bhf[7][2];
            #pragma unroll
            for (int nt = 0; nt < 7; ++nt) {
                uint32_t off = (uint32_t)(((nt * 8 + bn_off) * PB + k0 + bk_off) * 2);
                ldx2(bhf[nt], bhB + off);
            }
            const int cs = (k0 + fcol) ^ sw;
            #pragma unroll
            for (int mt = 0; mt < 2; ++mt) {
                const int rb = wid * 32 + mt * 16 + frow;
                const float* Ar0 = A + rb * KC;
                const float* Ar8 = A + (rb + 8) * KC;
                float2 t0 = *(const float2*)(Ar0 + cs);
                float2 t1 = *(const float2*)(Ar8 + cs);
                float2 t2 = *(const float2*)(Ar0 + (cs ^ 8));
                float2 t3 = *(const float2*)(Ar8 + (cs ^ 8));
                uint32_t av[4];
                av[0] = pack_bf2(t0.x, t0.y);
                av[1] = pack_bf2(t1.x, t1.y);
                av[2] = pack_bf2(t2.x, t2.y);
                av[3] = pack_bf2(t3.x, t3.y);
                #pragma unroll
                for (int nt = 0; nt < 7; ++nt)
                    mma16816(acc[mt][nt], av, bhf[nt]);
            }
        }
        __syncthreads();   // all warps done reading cur before it is restaged
    }

    // ---- epilogue: scores.
    #pragma unroll
    for (int mt = 0; mt < 2; ++mt) {
        float plo = 0.0f, phi = 0.0f;
        #pragma unroll
        for (int nt = 0; nt < 7; ++nt) {
            int c = nt * 8 + 2 * (lane & 3);
            plo += tanh_fast(acc[mt][nt][0] + sm.sb[c])     * sm.su[c];
            plo += tanh_fast(acc[mt][nt][1] + sm.sb[c + 1]) * sm.su[c + 1];
            phi += tanh_fast(acc[mt][nt][2] + sm.sb[c])     * sm.su[c];
            phi += tanh_fast(acc[mt][nt][3] + sm.sb[c + 1]) * sm.su[c + 1];
        }
        plo += __shfl_xor_sync(0xFFFFFFFFu, plo, 1);
        plo += __shfl_xor_sync(0xFFFFFFFFu, plo, 2);
        phi += __shfl_xor_sync(0xFFFFFFFFu, phi, 1);
        phi += __shfl_xor_sync(0xFFFFFFFFu, phi, 2);
        if ((lane & 3) == 0) {
            int r = wid * 32 + mt * 16 + (lane >> 2);
            sm.se[r]     = __expf(plo);
            sm.se[r + 8] = __expf(phi);
        }
    }
    __syncthreads();

    float e = sm.se[tid];
    float s = e;
    #pragma unroll
    for (int o = 16; o; o >>= 1) s += __shfl_xor_sync(0xFFFFFFFFu, s, o);
    if (lane == 0) sm.wsum[wid] = s;
    __syncthreads();
    if (tid == 0)
        g_esum_part[blockIdx.x] = sm.wsum[0] + sm.wsum[1] + sm.wsum[2] + sm.wsum[3];

    // ---- fused pool over this CTA's 128 rows (x L2-hot, fp32).
    const int tc = tid >> 6;
    const int g  = tid & 63;
    const float* xb = x + (size_t)(row0 + tc * 64) * D_ + g * 4;

    float ax = 0.0f, ay = 0.0f, az = 0.0f, aw = 0.0f;
    #pragma unroll 8
    for (int tt = 0; tt < 64; ++tt) {
        float w  = sm.se[tc * 64 + tt];
        float4 v = *(const float4*)(xb + (size_t)tt * D_);
        ax += v.x * w; ay += v.y * w; az += v.z * w; aw += v.w * w;
    }
    if (tc == 1) {
        sm.pp[g][0] = ax; sm.pp[g][1] = ay; sm.pp[g][2] = az; sm.pp[g][3] = aw;
    }
    __syncthreads();
    if (tc == 0) {
        float4 r;
        r.x = ax + sm.pp[g][0];
        r.y = ay + sm.pp[g][1];
        r.z = az + sm.pp[g][2];
        r.w = aw + sm.pp[g][3];
        *(float4*)&g_pool_part[blockIdx.x * D_ + g * 4] = r;
    }

    // ---- last CTA of this batch finalizes out[b,:].
    __syncthreads();
    if (tid == 0) {
        __threadfence();
        int old = atomicAdd(&g_cnt[b], 1);
        sm.is_last = (old == 3);
    }
    __syncthreads();
    if (sm.is_last) {
        __threadfence();
        const float* ep = &g_esum_part[4 * b];
        float inv = 1.0f / (ep[0] + ep[1] + ep[2] + ep[3] + 1e-7f);
        int d = tid * 2;
        const float* pp = &g_pool_part[(4 * b) * D_ + d];
        float p0 = pp[0]     + pp[D_]     + pp[2 * D_]     + pp[3 * D_];
        float p1 = pp[1]     + pp[D_ + 1] + pp[2 * D_ + 1] + pp[3 * D_ + 1];
        float2 r;
        r.x = p0 * inv;
        r.y = p1 * inv;
        *(float2*)&out[b * D_ + d] = r;
    }
}

extern "C" void kernel_launch(void* const* d_in, const int* in_sizes, int n_in,
                              void* d_out, int out_size)
{
    const float* x  = (const float*)d_in[0];
    const float* W  = (const float*)d_in[1];
    const float* bb = (const float*)d_in[2];
    const float* u  = (const float*)d_in[3];
    float* out = (float*)d_out;

    prep_kernel<<<(NP * D_ + 511) / 512, 512>>>(W);
    score_pool_mma<<<(B_ * T_) / ROWS, 128>>>(x, bb, u, out);
}